// round 16
// baseline (speedup 1.0000x reference)
#include <cuda_runtime.h>
#include <cuda_bf16.h>
#include <cstdint>
#include <math.h>

#define NTOK 768
#define DMODEL 256
#define NHEAD 8

// ---------------- scratch (device globals; no allocations allowed) ----------
__device__ __nv_bfloat16 g_qkv_bf[NTOK * 768];
__device__ __nv_bfloat16 g_vT_bf[NHEAD * 32 * NTOK];
__device__ __nv_bfloat16 g_att_bf[NTOK * DMODEL];
__device__ __nv_bfloat16 g_Bp_bf[NTOK * DMODEL];
__device__ float g_Ap[NTOK * DMODEL];
// split-KV attention scratch (3 splits)
__device__ float g_osplit[3 * NTOK * DMODEL];
__device__ float g_msplit[3 * NHEAD * NTOK];
__device__ float g_lsplit[3 * NHEAD * NTOK];

// ---------------- helpers ----------------------------------------------------
__device__ __forceinline__ void mma_bf16(float* c, unsigned a0, unsigned a1,
                                         unsigned a2, unsigned a3,
                                         unsigned b0, unsigned b1)
{
    asm volatile(
        "mma.sync.aligned.m16n8k16.row.col.f32.bf16.bf16.f32 "
        "{%0,%1,%2,%3}, {%4,%5,%6,%7}, {%8,%9}, {%0,%1,%2,%3};"
        : "+f"(c[0]), "+f"(c[1]), "+f"(c[2]), "+f"(c[3])
        : "r"(a0), "r"(a1), "r"(a2), "r"(a3), "r"(b0), "r"(b1));
}
__device__ __forceinline__ unsigned pack_bf16(float a, float b)
{
    __nv_bfloat162 h;
    h.x = __float2bfloat16_rn(a);
    h.y = __float2bfloat16_rn(b);
    return *reinterpret_cast<unsigned*>(&h);
}
__device__ __forceinline__ float2 unpack_bf16(unsigned u)
{
    __nv_bfloat162 h = *reinterpret_cast<__nv_bfloat162*>(&u);
    return make_float2(__bfloat162float(h.x), __bfloat162float(h.y));
}
__device__ __forceinline__ uint4 pack8(float4 a, float4 b)
{
    return make_uint4(pack_bf16(a.x, a.y), pack_bf16(a.z, a.w),
                      pack_bf16(b.x, b.y), pack_bf16(b.z, b.w));
}
__device__ __forceinline__ float fexp2(float x)
{
    float y;
    asm("ex2.approx.ftz.f32 %0, %1;" : "=f"(y) : "f"(x));
    return y;
}

// ---------------- GEMM 1: qkv = feat @ in_w^T + in_b (inline cvt, vT scatter)
#define GEMM_SMEM_U32 33792
#define GEMM_SMEM_BYTES (GEMM_SMEM_U32 * 4)

__global__ __launch_bounds__(256, 1) void gemm_qkv(
    const float4* __restrict__ A4f,   // features [768][64 f4]
    const float4* __restrict__ B4f,   // in_w [768][64 f4]
    const float* __restrict__ bias)
{
    extern __shared__ uint32_t sg[];
    uint32_t* As = sg;
    uint32_t* Bs = sg + 16896;

    const int m0 = blockIdx.y * 128;
    const int n0 = blockIdx.x * 128;
    const int t  = threadIdx.x;
    const int w  = t >> 5;
    const int lane = t & 31;
    const int g   = lane >> 2;
    const int tig = lane & 3;
    const int r0i = w * 16 + g, r1i = r0i + 8;

    for (int idx = t; idx < 4096; idx += 256) {
        int r = idx >> 5, c4 = idx & 31;
        float4 a0 = A4f[(m0 + r) * 64 + c4 * 2];
        float4 a1 = A4f[(m0 + r) * 64 + c4 * 2 + 1];
        *(uint4*)&As[r * 132 + c4 * 4] = pack8(a0, a1);
        float4 b0 = B4f[(n0 + r) * 64 + c4 * 2];
        float4 b1 = B4f[(n0 + r) * 64 + c4 * 2 + 1];
        *(uint4*)&Bs[r * 132 + c4 * 4] = pack8(b0, b1);
    }
    __syncthreads();

    float acc[16][4];
#pragma unroll
    for (int nt = 0; nt < 16; nt++)
#pragma unroll
        for (int q = 0; q < 4; q++) acc[nt][q] = 0.f;

#pragma unroll
    for (int q = 0; q < 16; q++) {
        uint32_t a0 = As[r0i * 132 + 8 * q + tig];
        uint32_t a1 = As[r1i * 132 + 8 * q + tig];
        uint32_t a2 = As[r0i * 132 + 8 * q + 4 + tig];
        uint32_t a3 = As[r1i * 132 + 8 * q + 4 + tig];
#pragma unroll
        for (int nt = 0; nt < 16; nt++) {
            int n = 8 * nt + g;
            uint32_t b0 = Bs[n * 132 + 8 * q + tig];
            uint32_t b1 = Bs[n * 132 + 8 * q + 4 + tig];
            mma_bf16(acc[nt], a0, a1, a2, a3, b0, b1);
        }
    }

    uint32_t* Cb = (uint32_t*)g_qkv_bf;
    const int gm0 = m0 + r0i, gm1 = m0 + r1i;
#pragma unroll
    for (int nt = 0; nt < 16; nt++) {
        int gn = n0 + 8 * nt + 2 * tig;
        float bi0 = bias[gn], bi1 = bias[gn + 1];
        float v00 = acc[nt][0] + bi0, v01 = acc[nt][1] + bi1;
        float v10 = acc[nt][2] + bi0, v11 = acc[nt][3] + bi1;
        Cb[gm0 * 384 + (gn >> 1)] = pack_bf16(v00, v01);
        Cb[gm1 * 384 + (gn >> 1)] = pack_bf16(v10, v11);
        if (gn >= 512) {
            int vr = gn - 512;
            g_vT_bf[vr * 768 + gm0]       = __float2bfloat16_rn(v00);
            g_vT_bf[(vr + 1) * 768 + gm0] = __float2bfloat16_rn(v01);
            g_vT_bf[vr * 768 + gm1]       = __float2bfloat16_rn(v10);
            g_vT_bf[(vr + 1) * 768 + gm1] = __float2bfloat16_rn(v11);
        }
    }
}

// ---------------- split-KV flash attention (3 splits x 2 k-tiles) ------------
__global__ __launch_bounds__(256, 1) void attn_flash()
{
    __shared__ uint32_t Ks[128 * 20];
    __shared__ uint32_t VTs[32 * 68];

    const int q0 = blockIdx.x * 128;
    const int h  = blockIdx.y;
    const int s  = blockIdx.z;
    const int t  = threadIdx.x;
    const int w  = t >> 5;
    const int lane = t & 31;
    const int g   = lane >> 2;
    const int tig = lane & 3;
    const int r0i = w * 16 + g, r1i = r0i + 8;

    const uint32_t* qkvU = (const uint32_t*)g_qkv_bf;
    const uint32_t* vtU  = (const uint32_t*)g_vT_bf;

    const float CS = 1.4426950408889634f * 0.17677669529663687f;

    uint32_t qf[8];
#pragma unroll
    for (int qq = 0; qq < 2; qq++) {
        qf[4 * qq]     = qkvU[(q0 + r0i) * 384 + h * 16 + 8 * qq + tig];
        qf[4 * qq + 1] = qkvU[(q0 + r1i) * 384 + h * 16 + 8 * qq + tig];
        qf[4 * qq + 2] = qkvU[(q0 + r0i) * 384 + h * 16 + 8 * qq + 4 + tig];
        qf[4 * qq + 3] = qkvU[(q0 + r1i) * 384 + h * 16 + 8 * qq + 4 + tig];
    }

    float acc_o[4][4];
#pragma unroll
    for (int nt = 0; nt < 4; nt++)
#pragma unroll
        for (int e = 0; e < 4; e++) acc_o[nt][e] = 0.f;
    float m0s = -1e30f, m1s = -1e30f, l0p = 0.f, l1p = 0.f;

    for (int kk = 0; kk < 2; kk++) {
        const int kt = s * 2 + kk;
        __syncthreads();
        for (int idx = t; idx < 2048; idx += 256) {
            int r = idx >> 4, c = idx & 15;
            Ks[r * 20 + c] = qkvU[(kt * 128 + r) * 384 + 128 + h * 16 + c];
        }
        for (int idx = t; idx < 2048; idx += 256) {
            int d = idx >> 6, c = idx & 63;
            VTs[d * 68 + c] = vtU[(h * 32 + d) * 384 + kt * 64 + c];
        }
        __syncthreads();

        float accs[16][4];
#pragma unroll
        for (int nt = 0; nt < 16; nt++)
#pragma unroll
            for (int e = 0; e < 4; e++) accs[nt][e] = 0.f;
#pragma unroll
        for (int qq = 0; qq < 2; qq++) {
            uint32_t a0 = qf[4 * qq], a1 = qf[4 * qq + 1];
            uint32_t a2 = qf[4 * qq + 2], a3 = qf[4 * qq + 3];
#pragma unroll
            for (int nt = 0; nt < 16; nt++) {
                int n = 8 * nt + g;
                uint32_t b0 = Ks[n * 20 + 8 * qq + tig];
                uint32_t b1 = Ks[n * 20 + 8 * qq + 4 + tig];
                mma_bf16(accs[nt], a0, a1, a2, a3, b0, b1);
            }
        }
        float lm0 = -1e30f, lm1 = -1e30f;
#pragma unroll
        for (int nt = 0; nt < 16; nt++) {
            accs[nt][0] *= CS; accs[nt][1] *= CS;
            accs[nt][2] *= CS; accs[nt][3] *= CS;
            lm0 = fmaxf(lm0, fmaxf(accs[nt][0], accs[nt][1]));
            lm1 = fmaxf(lm1, fmaxf(accs[nt][2], accs[nt][3]));
        }
#pragma unroll
        for (int o = 1; o <= 2; o <<= 1) {
            lm0 = fmaxf(lm0, __shfl_xor_sync(0xffffffffu, lm0, o));
            lm1 = fmaxf(lm1, __shfl_xor_sync(0xffffffffu, lm1, o));
        }
        float mn0 = fmaxf(m0s, lm0), mn1 = fmaxf(m1s, lm1);
        float al0 = fexp2(m0s - mn0), al1 = fexp2(m1s - mn1);
        m0s = mn0; m1s = mn1;

        float ps0 = 0.f, ps1 = 0.f;
        uint32_t Pf[32];
#pragma unroll
        for (int nt = 0; nt < 16; nt++) {
            float p00 = fexp2(accs[nt][0] - mn0);
            float p01 = fexp2(accs[nt][1] - mn0);
            float p10 = fexp2(accs[nt][2] - mn1);
            float p11 = fexp2(accs[nt][3] - mn1);
            ps0 += p00 + p01; ps1 += p10 + p11;
            int q2 = nt >> 1, off = (nt & 1) * 2;
            Pf[4 * q2 + off]     = pack_bf16(p00, p01);
            Pf[4 * q2 + off + 1] = pack_bf16(p10, p11);
        }
        l0p = l0p * al0 + ps0;
        l1p = l1p * al1 + ps1;
#pragma unroll
        for (int nt = 0; nt < 4; nt++) {
            acc_o[nt][0] *= al0; acc_o[nt][1] *= al0;
            acc_o[nt][2] *= al1; acc_o[nt][3] *= al1;
        }
#pragma unroll
        for (int q = 0; q < 8; q++) {
            uint32_t a0 = Pf[4 * q], a1 = Pf[4 * q + 1];
            uint32_t a2 = Pf[4 * q + 2], a3 = Pf[4 * q + 3];
#pragma unroll
            for (int nt = 0; nt < 4; nt++) {
                int n = 8 * nt + g;
                uint32_t b0 = VTs[n * 68 + 8 * q + tig];
                uint32_t b1 = VTs[n * 68 + 8 * q + 4 + tig];
                mma_bf16(acc_o[nt], a0, a1, a2, a3, b0, b1);
            }
        }
    }

#pragma unroll
    for (int o = 1; o <= 2; o <<= 1) {
        l0p += __shfl_xor_sync(0xffffffffu, l0p, o);
        l1p += __shfl_xor_sync(0xffffffffu, l1p, o);
    }
    float* oS = g_osplit + s * NTOK * DMODEL;
#pragma unroll
    for (int nt = 0; nt < 4; nt++) {
        *(float2*)&oS[(q0 + r0i) * 256 + h * 32 + 8 * nt + 2 * tig] =
            make_float2(acc_o[nt][0], acc_o[nt][1]);
        *(float2*)&oS[(q0 + r1i) * 256 + h * 32 + 8 * nt + 2 * tig] =
            make_float2(acc_o[nt][2], acc_o[nt][3]);
    }
    if (tig == 0) {
        g_msplit[s * 6144 + h * 768 + q0 + r0i] = m0s;
        g_lsplit[s * 6144 + h * 768 + q0 + r0i] = l0p;
        g_msplit[s * 6144 + h * 768 + q0 + r1i] = m1s;
        g_lsplit[s * 6144 + h * 768 + q0 + r1i] = l1p;
    }
}

// ---------------- GEMM 2: att = combine(osplit) @ out_w^T + out_b ------------
#define ATT_SMEM_U32 (33792 + 3072)
#define ATT_SMEM_BYTES (ATT_SMEM_U32 * 4)

__global__ __launch_bounds__(256, 1) void gemm_att(
    const float4* __restrict__ B4f,   // out_w fp32 [256][64 f4]
    const float* __restrict__ bias)
{
    extern __shared__ uint32_t sg[];
    uint32_t* As = sg;
    uint32_t* Bs = sg + 16896;
    float* sSc = (float*)(sg + 33792);   // [3][8][128]

    const int m0 = blockIdx.y * 128;
    const int n0 = blockIdx.x * 128;
    const int t  = threadIdx.x;
    const int w  = t >> 5;
    const int lane = t & 31;
    const int g   = lane >> 2;
    const int tig = lane & 3;
    const int r0i = w * 16 + g, r1i = r0i + 8;

    // per-(head,row) combine scales
#pragma unroll
    for (int p = 0; p < 4; p++) {
        int idx = t + p * 256;           // (h, r)
        int h = idx >> 7, r = idx & 127;
        int row = m0 + r;
        float m0v = g_msplit[h * 768 + row];
        float m1v = g_msplit[6144 + h * 768 + row];
        float m2v = g_msplit[12288 + h * 768 + row];
        float M = fmaxf(m0v, fmaxf(m1v, m2v));
        float e0 = fexp2(m0v - M), e1 = fexp2(m1v - M), e2 = fexp2(m2v - M);
        float inv = 1.f / (g_lsplit[h * 768 + row] * e0
                         + g_lsplit[6144 + h * 768 + row] * e1
                         + g_lsplit[12288 + h * 768 + row] * e2);
        sSc[idx]        = e0 * inv;
        sSc[1024 + idx] = e1 * inv;
        sSc[2048 + idx] = e2 * inv;
    }
    __syncthreads();

    for (int idx = t; idx < 4096; idx += 256) {
        int r = idx >> 5, c4 = idx & 31;
        int row = m0 + r;
        int h = c4 >> 2;
        float s0 = sSc[h * 128 + r];
        float s1 = sSc[1024 + h * 128 + r];
        float s2 = sSc[2048 + h * 128 + r];
        const float4* o0 = (const float4*)&g_osplit[row * 256 + c4 * 8];
        const float4* o1 = (const float4*)&g_osplit[196608 + row * 256 + c4 * 8];
        const float4* o2 = (const float4*)&g_osplit[393216 + row * 256 + c4 * 8];
        float4 a0, a1;
        {
            float4 x0 = o0[0], x1 = o1[0], x2 = o2[0];
            a0 = make_float4(x0.x * s0 + x1.x * s1 + x2.x * s2,
                             x0.y * s0 + x1.y * s1 + x2.y * s2,
                             x0.z * s0 + x1.z * s1 + x2.z * s2,
                             x0.w * s0 + x1.w * s1 + x2.w * s2);
            x0 = o0[1]; x1 = o1[1]; x2 = o2[1];
            a1 = make_float4(x0.x * s0 + x1.x * s1 + x2.x * s2,
                             x0.y * s0 + x1.y * s1 + x2.y * s2,
                             x0.z * s0 + x1.z * s1 + x2.z * s2,
                             x0.w * s0 + x1.w * s1 + x2.w * s2);
        }
        *(uint4*)&As[r * 132 + c4 * 4] = pack8(a0, a1);
        float4 b0 = B4f[(n0 + r) * 64 + c4 * 2];
        float4 b1 = B4f[(n0 + r) * 64 + c4 * 2 + 1];
        *(uint4*)&Bs[r * 132 + c4 * 4] = pack8(b0, b1);
    }
    __syncthreads();

    float acc[16][4];
#pragma unroll
    for (int nt = 0; nt < 16; nt++)
#pragma unroll
        for (int q = 0; q < 4; q++) acc[nt][q] = 0.f;

#pragma unroll
    for (int q = 0; q < 16; q++) {
        uint32_t a0 = As[r0i * 132 + 8 * q + tig];
        uint32_t a1 = As[r1i * 132 + 8 * q + tig];
        uint32_t a2 = As[r0i * 132 + 8 * q + 4 + tig];
        uint32_t a3 = As[r1i * 132 + 8 * q + 4 + tig];
#pragma unroll
        for (int nt = 0; nt < 16; nt++) {
            int n = 8 * nt + g;
            uint32_t b0 = Bs[n * 132 + 8 * q + tig];
            uint32_t b1 = Bs[n * 132 + 8 * q + 4 + tig];
            mma_bf16(acc[nt], a0, a1, a2, a3, b0, b1);
        }
    }

    uint32_t* Cb = (uint32_t*)g_att_bf;
    const int gm0 = m0 + r0i, gm1 = m0 + r1i;
#pragma unroll
    for (int nt = 0; nt < 16; nt++) {
        int gn = n0 + 8 * nt + 2 * tig;
        float bi0 = bias[gn], bi1 = bias[gn + 1];
        Cb[gm0 * 128 + (gn >> 1)] = pack_bf16(acc[nt][0] + bi0, acc[nt][1] + bi1);
        Cb[gm1 * 128 + (gn >> 1)] = pack_bf16(acc[nt][2] + bi0, acc[nt][3] + bi1);
    }
}

// ---------------- GEMM 3: [Ap | Bp] = att @ [w1a;w1b]^T + [b1|0] -------------
__global__ __launch_bounds__(256, 1) void gemm_apbp(
    const uint4* __restrict__ A4,    // att_bf [768][16 uint4]
    const float* __restrict__ w1,
    const float* __restrict__ b1)
{
    extern __shared__ uint32_t sg[];
    uint32_t* As = sg;
    uint32_t* Bs = sg + 16896;

    const int m0 = blockIdx.y * 128;
    const int n0 = blockIdx.x * 128;
    const int t  = threadIdx.x;
    const int w  = t >> 5;
    const int lane = t & 31;
    const int g   = lane >> 2;
    const int tig = lane & 3;
    const int r0i = w * 16 + g, r1i = r0i + 8;

    for (int idx = t; idx < 2048; idx += 256) {
        int r = idx >> 4, c4 = idx & 15;
        *(uint4*)&As[r * 132 + c4 * 4] = A4[(m0 + r) * 16 + c4];
    }
    for (int idx = t; idx < 4096; idx += 256) {
        int r = idx >> 5, c4 = idx & 31;
        int grow = n0 + r;
        const float* wr = (grow < 256) ? (w1 + grow * 771)
                                       : (w1 + (grow - 256) * 771 + 256);
        int d = c4 * 8;
        *(uint4*)&Bs[r * 132 + c4 * 4] = make_uint4(
            pack_bf16(wr[d], wr[d + 1]), pack_bf16(wr[d + 2], wr[d + 3]),
            pack_bf16(wr[d + 4], wr[d + 5]), pack_bf16(wr[d + 6], wr[d + 7]));
    }
    __syncthreads();

    float acc[16][4];
#pragma unroll
    for (int nt = 0; nt < 16; nt++)
#pragma unroll
        for (int q = 0; q < 4; q++) acc[nt][q] = 0.f;

#pragma unroll
    for (int q = 0; q < 16; q++) {
        uint32_t a0 = As[r0i * 132 + 8 * q + tig];
        uint32_t a1 = As[r1i * 132 + 8 * q + tig];
        uint32_t a2 = As[r0i * 132 + 8 * q + 4 + tig];
        uint32_t a3 = As[r1i * 132 + 8 * q + 4 + tig];
#pragma unroll
        for (int nt = 0; nt < 16; nt++) {
            int n = 8 * nt + g;
            uint32_t b0 = Bs[n * 132 + 8 * q + tig];
            uint32_t b1 = Bs[n * 132 + 8 * q + 4 + tig];
            mma_bf16(acc[nt], a0, a1, a2, a3, b0, b1);
        }
    }

    uint32_t* Cb = (uint32_t*)g_Bp_bf;
    const int gm0 = m0 + r0i, gm1 = m0 + r1i;
#pragma unroll
    for (int nt = 0; nt < 16; nt++) {
        int gn = n0 + 8 * nt + 2 * tig;
        if (gn < 256) {
            float bi0 = b1[gn], bi1 = b1[gn + 1];
            *(float2*)&g_Ap[gm0 * 256 + gn] =
                make_float2(acc[nt][0] + bi0, acc[nt][1] + bi1);
            *(float2*)&g_Ap[gm1 * 256 + gn] =
                make_float2(acc[nt][2] + bi0, acc[nt][3] + bi1);
        } else {
            Cb[gm0 * 128 + ((gn - 256) >> 1)] = pack_bf16(acc[nt][0], acc[nt][1]);
            Cb[gm1 * 128 + ((gn - 256) >> 1)] = pack_bf16(acc[nt][2], acc[nt][3]);
        }
    }
}

// ---------------- persistent fused all-pairs MLP (R13/R14 proven) ------------
#define OFF_W1   0
#define OFF_W2   33792
#define OFF_W3   50688
#define OFF_W4   55040
#define OFF_PACK 56192
#define OFF_LGB  57216
#define OFF_B2   57728
#define OFF_B3   57856
#define OFF_B4   57920
#define OFF_W5   57952
#define OFF_B5   57984
#define SMEM_U32 57988
#define SMEM_BYTES (SMEM_U32 * 4)
#define NWORK    3072
#define NBLOCKS  148

__global__ __launch_bounds__(384, 1) void fused_pairs_reg(
    const float* __restrict__ boxes,
    const float* __restrict__ w1,
    const float* __restrict__ Ap,
    const uint32_t* __restrict__ attbf,
    const uint32_t* __restrict__ bpbf,
    const float4* __restrict__ w2f, const float4* __restrict__ w3f,
    const float4* __restrict__ w4f,
    const float* __restrict__ lng, const float* __restrict__ lnb,
    const float* __restrict__ b2, const float* __restrict__ b3,
    const float* __restrict__ b4,
    const float* __restrict__ w5, const float* __restrict__ b5,
    float* __restrict__ out)
{
    extern __shared__ uint32_t sm[];
    uint32_t* W1s = sm + OFF_W1;
    uint32_t* W2s = sm + OFF_W2;
    uint32_t* W3s = sm + OFF_W3;
    uint32_t* W4s = sm + OFF_W4;
    float4*   sPack = (float4*)(sm + OFF_PACK);
    float2*   sLgb  = (float2*)(sm + OFF_LGB);
    float*    sB2   = (float*)(sm + OFF_B2);
    float*    sB3   = (float*)(sm + OFF_B3);
    float*    sB4   = (float*)(sm + OFF_B4);
    float*    sW5   = (float*)(sm + OFF_W5);
    float*    sB5   = (float*)(sm + OFF_B5);

    const int t  = threadIdx.x;
    const int w  = t >> 5;
    const int lane = t & 31;
    const int g   = lane >> 2;
    const int tig = lane & 3;

    // ---- one-time staging (inline fp32 -> bf16)
    for (int idx = t; idx < 8192; idx += 384) {
        int r = idx >> 5, c4 = idx & 31;
        const float* wr = w1 + r * 771 + 512 + c4 * 8;
        *(uint4*)&W1s[r * 132 + c4 * 4] = make_uint4(
            pack_bf16(wr[0], wr[1]), pack_bf16(wr[2], wr[3]),
            pack_bf16(wr[4], wr[5]), pack_bf16(wr[6], wr[7]));
    }
    for (int idx = t; idx < 4096; idx += 384) {
        int r = idx >> 5, c4 = idx & 31;
        *(uint4*)&W2s[r * 132 + c4 * 4] =
            pack8(w2f[r * 64 + c4 * 2], w2f[r * 64 + c4 * 2 + 1]);
    }
    for (int idx = t; idx < 1024; idx += 384) {
        int r = idx >> 4, c4 = idx & 15;
        *(uint4*)&W3s[r * 68 + c4 * 4] =
            pack8(w3f[r * 32 + c4 * 2], w3f[r * 32 + c4 * 2 + 1]);
    }
    for (int idx = t; idx < 256; idx += 384) {
        int r = idx >> 3, c4 = idx & 7;
        *(uint4*)&W4s[r * 36 + c4 * 4] =
            pack8(w4f[r * 16 + c4 * 2], w4f[r * 16 + c4 * 2 + 1]);
    }
    if (t < 256) {
        int k = t;
        sPack[k] = make_float4(0.f, w1[k * 771 + 768],
                               w1[k * 771 + 769], w1[k * 771 + 770]);
        sLgb[k]  = make_float2(lng[k], lnb[k]);
        if (k < 128) sB2[k] = b2[k];
        if (k < 64)  sB3[k] = b3[k];
        if (k < 32)  { sB4[k] = b4[k]; sW5[k] = w5[k]; }
        if (k == 0)  sB5[0] = b5[0];
    }

    const int r0 = w * 16 + g, r1 = r0 + 8;

    for (int wk = blockIdx.x; wk < NWORK; wk += NBLOCKS) {
        const int i  = wk >> 2;
        const int j0 = (wk & 3) * 192;
        const int jr0 = j0 + r0, jr1 = j0 + r1;

        __syncthreads();
        if (t < 256) sPack[t].x = Ap[i * 256 + t];
        __syncthreads();

        float bxi = boxes[i * 4], byi = boxes[i * 4 + 1];
        float dy0 = byi - boxes[jr0 * 4 + 1];
        float dy1 = byi - boxes[jr1 * 4 + 1];
        float sx0 = fabsf(bxi - boxes[jr0 * 4]), sya0 = fabsf(dy0), sys0 = dy0;
        float sx1 = fabsf(bxi - boxes[jr1 * 4]), sya1 = fabsf(dy1), sys1 = dy1;

        uint32_t A1[64];
#pragma unroll
        for (int q = 0; q < 16; q++) {
            int p0 = 8 * q + tig, p1 = p0 + 4;
            float2 ai0 = unpack_bf16(attbf[i * 128 + p0]);
            float2 ai1 = unpack_bf16(attbf[i * 128 + p1]);
            float2 j00 = unpack_bf16(attbf[jr0 * 128 + p0]);
            float2 j10 = unpack_bf16(attbf[jr1 * 128 + p0]);
            float2 j01 = unpack_bf16(attbf[jr0 * 128 + p1]);
            float2 j11 = unpack_bf16(attbf[jr1 * 128 + p1]);
            A1[4 * q]     = pack_bf16(j00.x * ai0.x, j00.y * ai0.y);
            A1[4 * q + 1] = pack_bf16(j10.x * ai0.x, j10.y * ai0.y);
            A1[4 * q + 2] = pack_bf16(j01.x * ai1.x, j01.y * ai1.y);
            A1[4 * q + 3] = pack_bf16(j11.x * ai1.x, j11.y * ai1.y);
        }

        uint32_t H1[64];
        float sum0 = 0.f, sq0 = 0.f, sum1 = 0.f, sq1 = 0.f;
#pragma unroll
        for (int h = 0; h < 2; h++) {
            float acc[16][4];
#pragma unroll
            for (int ntl = 0; ntl < 16; ntl++)
#pragma unroll
                for (int q = 0; q < 4; q++) acc[ntl][q] = 0.f;

#pragma unroll
            for (int q = 0; q < 16; q++) {
                uint32_t a0 = A1[4 * q],     a1 = A1[4 * q + 1];
                uint32_t a2 = A1[4 * q + 2], a3 = A1[4 * q + 3];
#pragma unroll
                for (int ntl = 0; ntl < 16; ntl++) {
                    int n = (h * 16 + ntl) * 8 + g;
                    uint32_t b0 = W1s[n * 132 + 8 * q + tig];
                    uint32_t b1 = W1s[n * 132 + 8 * q + 4 + tig];
                    mma_bf16(acc[ntl], a0, a1, a2, a3, b0, b1);
                }
            }
#pragma unroll
            for (int ntl = 0; ntl < 16; ntl++) {
                int nt = h * 16 + ntl;
                int c0 = 8 * nt + 2 * tig;
                float4 p0 = sPack[c0], p1 = sPack[c0 + 1];
                float2 bp0 = unpack_bf16(bpbf[jr0 * 128 + 4 * nt + tig]);
                float2 bp1 = unpack_bf16(bpbf[jr1 * 128 + 4 * nt + tig]);
                float v00 = acc[ntl][0] + p0.x + sx0 * p0.y + sya0 * p0.z + sys0 * p0.w + bp0.x;
                float v01 = acc[ntl][1] + p1.x + sx0 * p1.y + sya0 * p1.z + sys0 * p1.w + bp0.y;
                float v10 = acc[ntl][2] + p0.x + sx1 * p0.y + sya1 * p0.z + sys1 * p0.w + bp1.x;
                float v11 = acc[ntl][3] + p1.x + sx1 * p1.y + sya1 * p1.z + sys1 * p1.w + bp1.y;
                v00 = fmaxf(v00, 0.f); v01 = fmaxf(v01, 0.f);
                v10 = fmaxf(v10, 0.f); v11 = fmaxf(v11, 0.f);
                sum0 += v00 + v01; sq0 += v00 * v00 + v01 * v01;
                sum1 += v10 + v11; sq1 += v10 * v10 + v11 * v11;
                int q2 = nt >> 1, off = (nt & 1) * 2;
                H1[4 * q2 + off]     = pack_bf16(v00, v01);
                H1[4 * q2 + off + 1] = pack_bf16(v10, v11);
            }
        }

#pragma unroll
        for (int o = 1; o <= 2; o <<= 1) {
            sum0 += __shfl_xor_sync(0xffffffffu, sum0, o);
            sq0  += __shfl_xor_sync(0xffffffffu, sq0,  o);
            sum1 += __shfl_xor_sync(0xffffffffu, sum1, o);
            sq1  += __shfl_xor_sync(0xffffffffu, sq1,  o);
        }
        float mu0 = sum0 * (1.f / 256.f);
        float rs0 = rsqrtf(sq0 * (1.f / 256.f) - mu0 * mu0 + 1e-5f);
        float mu1 = sum1 * (1.f / 256.f);
        float rs1 = rsqrtf(sq1 * (1.f / 256.f) - mu1 * mu1 + 1e-5f);
#pragma unroll
        for (int q = 0; q < 16; q++) {
#pragma unroll
            for (int e2 = 0; e2 < 2; e2++) {
                int col = 16 * q + 8 * e2 + 2 * tig;
                float2 gb0 = sLgb[col], gb1 = sLgb[col + 1];
#pragma unroll
                for (int e = 0; e < 2; e++) {
                    int idx = 4 * q + 2 * e2 + e;
                    float2 v = unpack_bf16(H1[idx]);
                    float m = e ? mu1 : mu0, rr = e ? rs1 : rs0;
                    H1[idx] = pack_bf16((v.x - m) * rr * gb0.x + gb0.y,
                                        (v.y - m) * rr * gb1.x + gb1.y);
                }
            }
        }

        uint32_t H2[32];
#pragma unroll
        for (int h = 0; h < 2; h++) {
            float acc[8][4];
#pragma unroll
            for (int ntl = 0; ntl < 8; ntl++)
#pragma unroll
                for (int q = 0; q < 4; q++) acc[ntl][q] = 0.f;
#pragma unroll
            for (int q = 0; q < 16; q++) {
                uint32_t a0 = H1[4 * q],     a1 = H1[4 * q + 1];
                uint32_t a2 = H1[4 * q + 2], a3 = H1[4 * q + 3];
#pragma unroll
                for (int ntl = 0; ntl < 8; ntl++) {
                    int n = (h * 8 + ntl) * 8 + g;
                    uint32_t b0 = W2s[n * 132 + 8 * q + tig];
                    uint32_t b1 = W2s[n * 132 + 8 * q + 4 + tig];
                    mma_bf16(acc[ntl], a0, a1, a2, a3, b0, b1);
                }
            }
#pragma unroll
            for (int ntl = 0; ntl < 8; ntl++) {
                int nt = h * 8 + ntl;
                int c0 = 8 * nt + 2 * tig;
                float v00 = fmaxf(acc[ntl][0] + sB2[c0], 0.f);
                float v01 = fmaxf(acc[ntl][1] + sB2[c0 + 1], 0.f);
                float v10 = fmaxf(acc[ntl][2] + sB2[c0], 0.f);
                float v11 = fmaxf(acc[ntl][3] + sB2[c0 + 1], 0.f);
                int q2 = nt >> 1, off = (nt & 1) * 2;
                H2[4 * q2 + off]     = pack_bf16(v00, v01);
                H2[4 * q2 + off + 1] = pack_bf16(v10, v11);
            }
        }

        uint32_t H3[16];
        {
            float acc[8][4];
#pragma unroll
            for (int ntl = 0; ntl < 8; ntl++)
#pragma unroll
                for (int q = 0; q < 4; q++) acc[ntl][q] = 0.f;
#pragma unroll
            for (int q = 0; q < 8; q++) {
                uint32_t a0 = H2[4 * q],     a1 = H2[4 * q + 1];
                uint32_t a2 = H2[4 * q + 2], a3 = H2[4 * q + 3];
#pragma unroll
                for (int ntl = 0; ntl < 8; ntl++) {
                    int n = ntl * 8 + g;
                    uint32_t b0 = W3s[n * 68 + 8 * q + tig];
                    uint32_t b1 = W3s[n * 68 + 8 * q + 4 + tig];
                    mma_bf16(acc[ntl], a0, a1, a2, a3, b0, b1);
                }
            }
#pragma unroll
            for (int nt = 0; nt < 8; nt++) {
                int c0 = 8 * nt + 2 * tig;
                float v00 = fmaxf(acc[nt][0] + sB3[c0], 0.f);
                float v01 = fmaxf(acc[nt][1] + sB3[c0 + 1], 0.f);
                float v10 = fmaxf(acc[nt][2] + sB3[c0], 0.f);
                float v11 = fmaxf(acc[nt][3] + sB3[c0 + 1], 0.f);
                int q2 = nt >> 1, off = (nt & 1) * 2;
                H3[4 * q2 + off]     = pack_bf16(v00, v01);
                H3[4 * q2 + off + 1] = pack_bf16(v10, v11);
            }
        }

        {
            float acc[4][4];
#pragma unroll
            for (int ntl = 0; ntl < 4; ntl++)
#pragma unroll
                for (int q = 0; q < 4; q++) acc[ntl][q] = 0.f;
#pragma unroll
            for (int q = 0; q < 4; q++) {
                uint32_t a0 = H3[4 * q],     a1 = H3[4 * q + 1];
                uint32_t a2 = H3[4 * q + 2], a3 = H3[4 * q + 3];
#pragma unroll
                for (int ntl = 0; ntl < 4; ntl++) {
                    int n = ntl * 8 + g;
                    uint32_t b0 = W4s[n * 36 + 8 * q + tig];
                    uint32_t b1 = W4s[n * 36 + 8 * q + 4 + tig];
                    mma_bf16(acc[ntl], a0, a1, a2, a3, b0, b1);
                }
            }
            float p0 = 0.f, p1 = 0.f;
#pragma unroll
            for (int nt = 0; nt < 4; nt++) {
                int c0 = 8 * nt + 2 * tig;
                p0 += fmaxf(acc[nt][0] + sB4[c0], 0.f) * sW5[c0]
                    + fmaxf(acc[nt][1] + sB4[c0 + 1], 0.f) * sW5[c0 + 1];
                p1 += fmaxf(acc[nt][2] + sB4[c0], 0.f) * sW5[c0]
                    + fmaxf(acc[nt][3] + sB4[c0 + 1], 0.f) * sW5[c0 + 1];
            }
#pragma unroll
            for (int o = 1; o <= 2; o <<= 1) {
                p0 += __shfl_xor_sync(0xffffffffu, p0, o);
                p1 += __shfl_xor_sync(0xffffffffu, p1, o);
            }
            if (tig == 0) {
                float bb = sB5[0];
                out[i * 768 + jr0] = (jr0 == i) ? -1000000000.0f : p0 + bb;
                out[i * 768 + jr1] = (jr1 == i) ? -1000000000.0f : p1 + bb;
            }
        }
    }
}

// ---------------- host launch ------------------------------------------------
extern "C" void kernel_launch(void* const* d_in, const int* in_sizes, int n_in,
                              void* d_out, int out_size)
{
    (void)in_sizes; (void)n_in; (void)out_size;
    const float* features = (const float*)d_in[0];
    const float* boxes    = (const float*)d_in[1];
    const float* in_w     = (const float*)d_in[2];
    const float* in_b     = (const float*)d_in[3];
    const float* out_w    = (const float*)d_in[4];
    const float* out_b    = (const float*)d_in[5];
    const float* w1       = (const float*)d_in[6];
    const float* b1       = (const float*)d_in[7];
    const float* lng      = (const float*)d_in[8];
    const float* lnb      = (const float*)d_in[9];
    const float* w2       = (const float*)d_in[10];
    const float* b2       = (const float*)d_in[11];
    const float* w3       = (const float*)d_in[12];
    const float* b3       = (const float*)d_in[13];
    const float* w4       = (const float*)d_in[14];
    const float* b4       = (const float*)d_in[15];
    const float* w5       = (const float*)d_in[16];
    const float* b5       = (const float*)d_in[17];
    float* out = (float*)d_out;

    void *attbf, *bpbf;
    float* Apb;
    cudaGetSymbolAddress(&attbf, g_att_bf);
    cudaGetSymbolAddress(&bpbf,  g_Bp_bf);
    cudaGetSymbolAddress((void**)&Apb, g_Ap);

    cudaFuncSetAttribute(gemm_qkv,
                         cudaFuncAttributeMaxDynamicSharedMemorySize, GEMM_SMEM_BYTES);
    cudaFuncSetAttribute(gemm_att,
                         cudaFuncAttributeMaxDynamicSharedMemorySize, ATT_SMEM_BYTES);
    cudaFuncSetAttribute(gemm_apbp,
                         cudaFuncAttributeMaxDynamicSharedMemorySize, GEMM_SMEM_BYTES);
    cudaFuncSetAttribute(fused_pairs_reg,
                         cudaFuncAttributeMaxDynamicSharedMemorySize, SMEM_BYTES);

    // 1. qkv = feat @ in_w^T + in_b  (inline cvt + fused vT scatter)
    gemm_qkv<<<dim3(6, 6), 256, GEMM_SMEM_BYTES>>>(
        (const float4*)features, (const float4*)in_w, in_b);

    // 2. split-KV flash attention (3 splits)
    attn_flash<<<dim3(6, 8, 3), 256>>>();

    // 3. att = combine(osplit) @ out_w^T + out_b  (inline combine + cvt)
    gemm_att<<<dim3(2, 6), 256, ATT_SMEM_BYTES>>>(
        (const float4*)out_w, out_b);

    // 4. [Ap | Bp] = att @ [w1a;w1b]^T + [b1|0]  (inline w1 cvt, split epilogue)
    gemm_apbp<<<dim3(4, 6), 256, GEMM_SMEM_BYTES>>>(
        (const uint4*)attbf, w1, b1);

    // 5. persistent fused all-pairs MLP (inline weight cvt, staged once)
    fused_pairs_reg<<<NBLOCKS, 384, SMEM_BYTES>>>(
        boxes, w1, Apb,
        (const uint32_t*)attbf, (const uint32_t*)bpbf,
        (const float4*)w2, (const float4*)w3, (const float4*)w4,
        lng, lnb, b2, b3, b4, w5, b5, out);
}

// round 17
// speedup vs baseline: 1.0164x; 1.0164x over previous
#include <cuda_runtime.h>
#include <cuda_bf16.h>
#include <cstdint>
#include <math.h>

#define NTOK 768
#define DMODEL 256
#define NHEAD 8

// ---------------- scratch (device globals; no allocations allowed) ----------
__device__ __nv_bfloat16 g_qkv_bf[NTOK * 768];
__device__ __nv_bfloat16 g_vT_bf[NHEAD * 32 * NTOK];
__device__ __nv_bfloat16 g_w1ab_bf[512 * 256];   // rows 0-255 w1a, 256-511 w1b
__device__ __nv_bfloat16 g_w1c_bf[256 * 256];
__device__ __nv_bfloat16 g_att_bf[NTOK * DMODEL];
__device__ __nv_bfloat16 g_Bp_bf[NTOK * DMODEL];
__device__ float g_Ap[NTOK * DMODEL];
// split-KV attention scratch (3 splits)
__device__ float g_osplit[3 * NTOK * DMODEL];
__device__ float g_msplit[3 * NHEAD * NTOK];
__device__ float g_lsplit[3 * NHEAD * NTOK];

// ---------------- helpers ----------------------------------------------------
__device__ __forceinline__ void mma_bf16(float* c, unsigned a0, unsigned a1,
                                         unsigned a2, unsigned a3,
                                         unsigned b0, unsigned b1)
{
    asm volatile(
        "mma.sync.aligned.m16n8k16.row.col.f32.bf16.bf16.f32 "
        "{%0,%1,%2,%3}, {%4,%5,%6,%7}, {%8,%9}, {%0,%1,%2,%3};"
        : "+f"(c[0]), "+f"(c[1]), "+f"(c[2]), "+f"(c[3])
        : "r"(a0), "r"(a1), "r"(a2), "r"(a3), "r"(b0), "r"(b1));
}
__device__ __forceinline__ unsigned pack_bf16(float a, float b)
{
    __nv_bfloat162 h;
    h.x = __float2bfloat16_rn(a);
    h.y = __float2bfloat16_rn(b);
    return *reinterpret_cast<unsigned*>(&h);
}
__device__ __forceinline__ float2 unpack_bf16(unsigned u)
{
    __nv_bfloat162 h = *reinterpret_cast<__nv_bfloat162*>(&u);
    return make_float2(__bfloat162float(h.x), __bfloat162float(h.y));
}
__device__ __forceinline__ uint4 pack8(float4 a, float4 b)
{
    return make_uint4(pack_bf16(a.x, a.y), pack_bf16(a.z, a.w),
                      pack_bf16(b.x, b.y), pack_bf16(b.z, b.w));
}
__device__ __forceinline__ float fexp2(float x)
{
    float y;
    asm("ex2.approx.ftz.f32 %0, %1;" : "=f"(y) : "f"(x));
    return y;
}

// ---------------- GEMM 1: qkv = feat @ in_w^T + in_b  (+vT scatter, +w1 cvt)
#define GEMM_SMEM_U32 33792
#define GEMM_SMEM_BYTES (GEMM_SMEM_U32 * 4)

__global__ __launch_bounds__(256, 1) void gemm_qkv(
    const float4* __restrict__ A4f,   // features [768][64 f4]
    const float4* __restrict__ B4f,   // in_w [768][64 f4]
    const float* __restrict__ bias,
    const float* __restrict__ w1)
{
    extern __shared__ uint32_t sg[];
    uint32_t* As = sg;
    uint32_t* Bs = sg + 16896;

    const int m0 = blockIdx.y * 128;
    const int n0 = blockIdx.x * 128;
    const int t  = threadIdx.x;
    const int w  = t >> 5;
    const int lane = t & 31;
    const int g   = lane >> 2;
    const int tig = lane & 3;
    const int r0i = w * 16 + g, r1i = r0i + 8;

    for (int idx = t; idx < 4096; idx += 256) {
        int r = idx >> 5, c4 = idx & 31;
        float4 a0 = A4f[(m0 + r) * 64 + c4 * 2];
        float4 a1 = A4f[(m0 + r) * 64 + c4 * 2 + 1];
        *(uint4*)&As[r * 132 + c4 * 4] = pack8(a0, a1);
        float4 b0 = B4f[(n0 + r) * 64 + c4 * 2];
        float4 b1 = B4f[(n0 + r) * 64 + c4 * 2 + 1];
        *(uint4*)&Bs[r * 132 + c4 * 4] = pack8(b0, b1);
    }
    __syncthreads();

    float acc[16][4];
#pragma unroll
    for (int nt = 0; nt < 16; nt++)
#pragma unroll
        for (int q = 0; q < 4; q++) acc[nt][q] = 0.f;

#pragma unroll
    for (int q = 0; q < 16; q++) {
        uint32_t a0 = As[r0i * 132 + 8 * q + tig];
        uint32_t a1 = As[r1i * 132 + 8 * q + tig];
        uint32_t a2 = As[r0i * 132 + 8 * q + 4 + tig];
        uint32_t a3 = As[r1i * 132 + 8 * q + 4 + tig];
#pragma unroll
        for (int nt = 0; nt < 16; nt++) {
            int n = 8 * nt + g;
            uint32_t b0 = Bs[n * 132 + 8 * q + tig];
            uint32_t b1 = Bs[n * 132 + 8 * q + 4 + tig];
            mma_bf16(acc[nt], a0, a1, a2, a3, b0, b1);
        }
    }

    uint32_t* Cb = (uint32_t*)g_qkv_bf;
    const int gm0 = m0 + r0i, gm1 = m0 + r1i;
#pragma unroll
    for (int nt = 0; nt < 16; nt++) {
        int gn = n0 + 8 * nt + 2 * tig;
        float bi0 = bias[gn], bi1 = bias[gn + 1];
        float v00 = acc[nt][0] + bi0, v01 = acc[nt][1] + bi1;
        float v10 = acc[nt][2] + bi0, v11 = acc[nt][3] + bi1;
        Cb[gm0 * 384 + (gn >> 1)] = pack_bf16(v00, v01);
        Cb[gm1 * 384 + (gn >> 1)] = pack_bf16(v10, v11);
        if (gn >= 512) {
            int vr = gn - 512;
            g_vT_bf[vr * 768 + gm0]       = __float2bfloat16_rn(v00);
            g_vT_bf[(vr + 1) * 768 + gm0] = __float2bfloat16_rn(v01);
            g_vT_bf[vr * 768 + gm1]       = __float2bfloat16_rn(v10);
            g_vT_bf[(vr + 1) * 768 + gm1] = __float2bfloat16_rn(v11);
        }
    }

    // ---- tail: convert w1a/w1b/w1c -> bf16 (coalesced along d)
    const int gid = (blockIdx.y * gridDim.x + blockIdx.x) * 256 + t;
    const int nthreads = gridDim.x * gridDim.y * 256;
    for (int idx = gid; idx < 3 * 65536; idx += nthreads) {
        int mat = idx >> 16, rem = idx & 65535;
        int n = rem >> 8, d = rem & 255;
        float v = w1[n * 771 + mat * 256 + d];
        if (mat < 2) g_w1ab_bf[mat * 65536 + rem] = __float2bfloat16_rn(v);
        else         g_w1c_bf[rem] = __float2bfloat16_rn(v);
    }
}

// ---------------- split-KV flash attention (3 splits x 2 k-tiles) ------------
__global__ __launch_bounds__(256, 1) void attn_flash()
{
    __shared__ uint32_t Ks[128 * 20];
    __shared__ uint32_t VTs[32 * 68];

    const int q0 = blockIdx.x * 128;
    const int h  = blockIdx.y;
    const int s  = blockIdx.z;
    const int t  = threadIdx.x;
    const int w  = t >> 5;
    const int lane = t & 31;
    const int g   = lane >> 2;
    const int tig = lane & 3;
    const int r0i = w * 16 + g, r1i = r0i + 8;

    const uint32_t* qkvU = (const uint32_t*)g_qkv_bf;
    const uint32_t* vtU  = (const uint32_t*)g_vT_bf;

    const float CS = 1.4426950408889634f * 0.17677669529663687f;

    uint32_t qf[8];
#pragma unroll
    for (int qq = 0; qq < 2; qq++) {
        qf[4 * qq]     = qkvU[(q0 + r0i) * 384 + h * 16 + 8 * qq + tig];
        qf[4 * qq + 1] = qkvU[(q0 + r1i) * 384 + h * 16 + 8 * qq + tig];
        qf[4 * qq + 2] = qkvU[(q0 + r0i) * 384 + h * 16 + 8 * qq + 4 + tig];
        qf[4 * qq + 3] = qkvU[(q0 + r1i) * 384 + h * 16 + 8 * qq + 4 + tig];
    }

    float acc_o[4][4];
#pragma unroll
    for (int nt = 0; nt < 4; nt++)
#pragma unroll
        for (int e = 0; e < 4; e++) acc_o[nt][e] = 0.f;
    float m0s = -1e30f, m1s = -1e30f, l0p = 0.f, l1p = 0.f;

    for (int kk = 0; kk < 2; kk++) {
        const int kt = s * 2 + kk;
        __syncthreads();
        for (int idx = t; idx < 2048; idx += 256) {
            int r = idx >> 4, c = idx & 15;
            Ks[r * 20 + c] = qkvU[(kt * 128 + r) * 384 + 128 + h * 16 + c];
        }
        for (int idx = t; idx < 2048; idx += 256) {
            int d = idx >> 6, c = idx & 63;
            VTs[d * 68 + c] = vtU[(h * 32 + d) * 384 + kt * 64 + c];
        }
        __syncthreads();

        float accs[16][4];
#pragma unroll
        for (int nt = 0; nt < 16; nt++)
#pragma unroll
            for (int e = 0; e < 4; e++) accs[nt][e] = 0.f;
#pragma unroll
        for (int qq = 0; qq < 2; qq++) {
            uint32_t a0 = qf[4 * qq], a1 = qf[4 * qq + 1];
            uint32_t a2 = qf[4 * qq + 2], a3 = qf[4 * qq + 3];
#pragma unroll
            for (int nt = 0; nt < 16; nt++) {
                int n = 8 * nt + g;
                uint32_t b0 = Ks[n * 20 + 8 * qq + tig];
                uint32_t b1 = Ks[n * 20 + 8 * qq + 4 + tig];
                mma_bf16(accs[nt], a0, a1, a2, a3, b0, b1);
            }
        }
        float lm0 = -1e30f, lm1 = -1e30f;
#pragma unroll
        for (int nt = 0; nt < 16; nt++) {
            accs[nt][0] *= CS; accs[nt][1] *= CS;
            accs[nt][2] *= CS; accs[nt][3] *= CS;
            lm0 = fmaxf(lm0, fmaxf(accs[nt][0], accs[nt][1]));
            lm1 = fmaxf(lm1, fmaxf(accs[nt][2], accs[nt][3]));
        }
#pragma unroll
        for (int o = 1; o <= 2; o <<= 1) {
            lm0 = fmaxf(lm0, __shfl_xor_sync(0xffffffffu, lm0, o));
            lm1 = fmaxf(lm1, __shfl_xor_sync(0xffffffffu, lm1, o));
        }
        float mn0 = fmaxf(m0s, lm0), mn1 = fmaxf(m1s, lm1);
        float al0 = fexp2(m0s - mn0), al1 = fexp2(m1s - mn1);
        m0s = mn0; m1s = mn1;

        float ps0 = 0.f, ps1 = 0.f;
        uint32_t Pf[32];
#pragma unroll
        for (int nt = 0; nt < 16; nt++) {
            float p00 = fexp2(accs[nt][0] - mn0);
            float p01 = fexp2(accs[nt][1] - mn0);
            float p10 = fexp2(accs[nt][2] - mn1);
            float p11 = fexp2(accs[nt][3] - mn1);
            ps0 += p00 + p01; ps1 += p10 + p11;
            int q2 = nt >> 1, off = (nt & 1) * 2;
            Pf[4 * q2 + off]     = pack_bf16(p00, p01);
            Pf[4 * q2 + off + 1] = pack_bf16(p10, p11);
        }
        l0p = l0p * al0 + ps0;
        l1p = l1p * al1 + ps1;
#pragma unroll
        for (int nt = 0; nt < 4; nt++) {
            acc_o[nt][0] *= al0; acc_o[nt][1] *= al0;
            acc_o[nt][2] *= al1; acc_o[nt][3] *= al1;
        }
#pragma unroll
        for (int q = 0; q < 8; q++) {
            uint32_t a0 = Pf[4 * q], a1 = Pf[4 * q + 1];
            uint32_t a2 = Pf[4 * q + 2], a3 = Pf[4 * q + 3];
#pragma unroll
            for (int nt = 0; nt < 4; nt++) {
                int n = 8 * nt + g;
                uint32_t b0 = VTs[n * 68 + 8 * q + tig];
                uint32_t b1 = VTs[n * 68 + 8 * q + 4 + tig];
                mma_bf16(acc_o[nt], a0, a1, a2, a3, b0, b1);
            }
        }
    }

#pragma unroll
    for (int o = 1; o <= 2; o <<= 1) {
        l0p += __shfl_xor_sync(0xffffffffu, l0p, o);
        l1p += __shfl_xor_sync(0xffffffffu, l1p, o);
    }
    float* oS = g_osplit + s * NTOK * DMODEL;
#pragma unroll
    for (int nt = 0; nt < 4; nt++) {
        *(float2*)&oS[(q0 + r0i) * 256 + h * 32 + 8 * nt + 2 * tig] =
            make_float2(acc_o[nt][0], acc_o[nt][1]);
        *(float2*)&oS[(q0 + r1i) * 256 + h * 32 + 8 * nt + 2 * tig] =
            make_float2(acc_o[nt][2], acc_o[nt][3]);
    }
    if (tig == 0) {
        g_msplit[s * 6144 + h * 768 + q0 + r0i] = m0s;
        g_lsplit[s * 6144 + h * 768 + q0 + r0i] = l0p;
        g_msplit[s * 6144 + h * 768 + q0 + r1i] = m1s;
        g_lsplit[s * 6144 + h * 768 + q0 + r1i] = l1p;
    }
}

// ---------------- GEMM 2: att = combine(osplit) @ out_w^T + out_b ------------
#define ATT_SMEM_U32 (33792 + 3072)
#define ATT_SMEM_BYTES (ATT_SMEM_U32 * 4)

__global__ __launch_bounds__(256, 1) void gemm_att(
    const float4* __restrict__ B4f,   // out_w fp32 [256][64 f4]
    const float* __restrict__ bias)
{
    extern __shared__ uint32_t sg[];
    uint32_t* As = sg;
    uint32_t* Bs = sg + 16896;
    float* sSc = (float*)(sg + 33792);   // [3][8][128]

    const int m0 = blockIdx.y * 128;
    const int n0 = blockIdx.x * 128;
    const int t  = threadIdx.x;
    const int w  = t >> 5;
    const int lane = t & 31;
    const int g   = lane >> 2;
    const int tig = lane & 3;
    const int r0i = w * 16 + g, r1i = r0i + 8;

#pragma unroll
    for (int p = 0; p < 4; p++) {
        int idx = t + p * 256;           // (h, r)
        int h = idx >> 7, r = idx & 127;
        int row = m0 + r;
        float m0v = g_msplit[h * 768 + row];
        float m1v = g_msplit[6144 + h * 768 + row];
        float m2v = g_msplit[12288 + h * 768 + row];
        float M = fmaxf(m0v, fmaxf(m1v, m2v));
        float e0 = fexp2(m0v - M), e1 = fexp2(m1v - M), e2 = fexp2(m2v - M);
        float inv = 1.f / (g_lsplit[h * 768 + row] * e0
                         + g_lsplit[6144 + h * 768 + row] * e1
                         + g_lsplit[12288 + h * 768 + row] * e2);
        sSc[idx]        = e0 * inv;
        sSc[1024 + idx] = e1 * inv;
        sSc[2048 + idx] = e2 * inv;
    }
    __syncthreads();

    for (int idx = t; idx < 4096; idx += 256) {
        int r = idx >> 5, c4 = idx & 31;
        int row = m0 + r;
        int h = c4 >> 2;
        float s0 = sSc[h * 128 + r];
        float s1 = sSc[1024 + h * 128 + r];
        float s2 = sSc[2048 + h * 128 + r];
        const float4* o0 = (const float4*)&g_osplit[row * 256 + c4 * 8];
        const float4* o1 = (const float4*)&g_osplit[196608 + row * 256 + c4 * 8];
        const float4* o2 = (const float4*)&g_osplit[393216 + row * 256 + c4 * 8];
        float4 a0, a1;
        {
            float4 x0 = o0[0], x1 = o1[0], x2 = o2[0];
            a0 = make_float4(x0.x * s0 + x1.x * s1 + x2.x * s2,
                             x0.y * s0 + x1.y * s1 + x2.y * s2,
                             x0.z * s0 + x1.z * s1 + x2.z * s2,
                             x0.w * s0 + x1.w * s1 + x2.w * s2);
            x0 = o0[1]; x1 = o1[1]; x2 = o2[1];
            a1 = make_float4(x0.x * s0 + x1.x * s1 + x2.x * s2,
                             x0.y * s0 + x1.y * s1 + x2.y * s2,
                             x0.z * s0 + x1.z * s1 + x2.z * s2,
                             x0.w * s0 + x1.w * s1 + x2.w * s2);
        }
        *(uint4*)&As[r * 132 + c4 * 4] = pack8(a0, a1);
        float4 b0 = B4f[(n0 + r) * 64 + c4 * 2];
        float4 b1 = B4f[(n0 + r) * 64 + c4 * 2 + 1];
        *(uint4*)&Bs[r * 132 + c4 * 4] = pack8(b0, b1);
    }
    __syncthreads();

    float acc[16][4];
#pragma unroll
    for (int nt = 0; nt < 16; nt++)
#pragma unroll
        for (int q = 0; q < 4; q++) acc[nt][q] = 0.f;

#pragma unroll
    for (int q = 0; q < 16; q++) {
        uint32_t a0 = As[r0i * 132 + 8 * q + tig];
        uint32_t a1 = As[r1i * 132 + 8 * q + tig];
        uint32_t a2 = As[r0i * 132 + 8 * q + 4 + tig];
        uint32_t a3 = As[r1i * 132 + 8 * q + 4 + tig];
#pragma unroll
        for (int nt = 0; nt < 16; nt++) {
            int n = 8 * nt + g;
            uint32_t b0 = Bs[n * 132 + 8 * q + tig];
            uint32_t b1 = Bs[n * 132 + 8 * q + 4 + tig];
            mma_bf16(acc[nt], a0, a1, a2, a3, b0, b1);
        }
    }

    uint32_t* Cb = (uint32_t*)g_att_bf;
    const int gm0 = m0 + r0i, gm1 = m0 + r1i;
#pragma unroll
    for (int nt = 0; nt < 16; nt++) {
        int gn = n0 + 8 * nt + 2 * tig;
        float bi0 = bias[gn], bi1 = bias[gn + 1];
        Cb[gm0 * 128 + (gn >> 1)] = pack_bf16(acc[nt][0] + bi0, acc[nt][1] + bi1);
        Cb[gm1 * 128 + (gn >> 1)] = pack_bf16(acc[nt][2] + bi0, acc[nt][3] + bi1);
    }
}

// ---------------- GEMM 3: [Ap | Bp] = att @ [w1a;w1b]^T + [b1|0] -------------
__global__ __launch_bounds__(256, 1) void gemm_apbp(
    const uint4* __restrict__ A4,     // att_bf [768][16 uint4]
    const uint4* __restrict__ B4,     // w1ab_bf [512][16 uint4]
    const float* __restrict__ b1)
{
    extern __shared__ uint32_t sg[];
    uint32_t* As = sg;
    uint32_t* Bs = sg + 16896;

    const int m0 = blockIdx.y * 128;
    const int n0 = blockIdx.x * 128;
    const int t  = threadIdx.x;
    const int w  = t >> 5;
    const int lane = t & 31;
    const int g   = lane >> 2;
    const int tig = lane & 3;
    const int r0i = w * 16 + g, r1i = r0i + 8;

    for (int idx = t; idx < 2048; idx += 256) {
        int r = idx >> 4, c4 = idx & 15;
        *(uint4*)&As[r * 132 + c4 * 4] = A4[(m0 + r) * 16 + c4];
        *(uint4*)&Bs[r * 132 + c4 * 4] = B4[(n0 + r) * 16 + c4];
    }
    __syncthreads();

    float acc[16][4];
#pragma unroll
    for (int nt = 0; nt < 16; nt++)
#pragma unroll
        for (int q = 0; q < 4; q++) acc[nt][q] = 0.f;

#pragma unroll
    for (int q = 0; q < 16; q++) {
        uint32_t a0 = As[r0i * 132 + 8 * q + tig];
        uint32_t a1 = As[r1i * 132 + 8 * q + tig];
        uint32_t a2 = As[r0i * 132 + 8 * q + 4 + tig];
        uint32_t a3 = As[r1i * 132 + 8 * q + 4 + tig];
#pragma unroll
        for (int nt = 0; nt < 16; nt++) {
            int n = 8 * nt + g;
            uint32_t b0 = Bs[n * 132 + 8 * q + tig];
            uint32_t b1 = Bs[n * 132 + 8 * q + 4 + tig];
            mma_bf16(acc[nt], a0, a1, a2, a3, b0, b1);
        }
    }

    uint32_t* Cb = (uint32_t*)g_Bp_bf;
    const int gm0 = m0 + r0i, gm1 = m0 + r1i;
#pragma unroll
    for (int nt = 0; nt < 16; nt++) {
        int gn = n0 + 8 * nt + 2 * tig;
        if (gn < 256) {
            float bi0 = b1[gn], bi1 = b1[gn + 1];
            *(float2*)&g_Ap[gm0 * 256 + gn] =
                make_float2(acc[nt][0] + bi0, acc[nt][1] + bi1);
            *(float2*)&g_Ap[gm1 * 256 + gn] =
                make_float2(acc[nt][2] + bi0, acc[nt][3] + bi1);
        } else {
            Cb[gm0 * 128 + ((gn - 256) >> 1)] = pack_bf16(acc[nt][0], acc[nt][1]);
            Cb[gm1 * 128 + ((gn - 256) >> 1)] = pack_bf16(acc[nt][2], acc[nt][3]);
        }
    }
}

// ---------------- persistent fused all-pairs MLP (R13/R14 proven) ------------
#define OFF_W1   0
#define OFF_W2   33792
#define OFF_W3   50688
#define OFF_W4   55040
#define OFF_PACK 56192
#define OFF_LGB  57216
#define OFF_B2   57728
#define OFF_B3   57856
#define OFF_B4   57920
#define OFF_W5   57952
#define OFF_B5   57984
#define SMEM_U32 57988
#define SMEM_BYTES (SMEM_U32 * 4)
#define NWORK    3072
#define NBLOCKS  148

__global__ __launch_bounds__(384, 1) void fused_pairs_reg(
    const float* __restrict__ boxes,
    const float* __restrict__ w1,
    const float* __restrict__ Ap,
    const uint32_t* __restrict__ attbf,
    const uint32_t* __restrict__ bpbf,
    const uint4* __restrict__ w1v,
    const float4* __restrict__ w2f, const float4* __restrict__ w3f,
    const float4* __restrict__ w4f,
    const float* __restrict__ lng, const float* __restrict__ lnb,
    const float* __restrict__ b2, const float* __restrict__ b3,
    const float* __restrict__ b4,
    const float* __restrict__ w5, const float* __restrict__ b5,
    float* __restrict__ out)
{
    extern __shared__ uint32_t sm[];
    uint32_t* W1s = sm + OFF_W1;
    uint32_t* W2s = sm + OFF_W2;
    uint32_t* W3s = sm + OFF_W3;
    uint32_t* W4s = sm + OFF_W4;
    float4*   sPack = (float4*)(sm + OFF_PACK);
    float2*   sLgb  = (float2*)(sm + OFF_LGB);
    float*    sB2   = (float*)(sm + OFF_B2);
    float*    sB3   = (float*)(sm + OFF_B3);
    float*    sB4   = (float*)(sm + OFF_B4);
    float*    sW5   = (float*)(sm + OFF_W5);
    float*    sB5   = (float*)(sm + OFF_B5);

    const int t  = threadIdx.x;
    const int w  = t >> 5;
    const int lane = t & 31;
    const int g   = lane >> 2;
    const int tig = lane & 3;

    // ---- one-time staging
    for (int idx = t; idx < 8192; idx += 384) {
        int r = idx >> 5, c4 = idx & 31;
        *(uint4*)&W1s[r * 132 + c4 * 4] = w1v[r * 32 + c4];
    }
    for (int idx = t; idx < 4096; idx += 384) {
        int r = idx >> 5, c4 = idx & 31;
        *(uint4*)&W2s[r * 132 + c4 * 4] =
            pack8(w2f[r * 64 + c4 * 2], w2f[r * 64 + c4 * 2 + 1]);
    }
    for (int idx = t; idx < 1024; idx += 384) {
        int r = idx >> 4, c4 = idx & 15;
        *(uint4*)&W3s[r * 68 + c4 * 4] =
            pack8(w3f[r * 32 + c4 * 2], w3f[r * 32 + c4 * 2 + 1]);
    }
    for (int idx = t; idx < 256; idx += 384) {
        int r = idx >> 3, c4 = idx & 7;
        *(uint4*)&W4s[r * 36 + c4 * 4] =
            pack8(w4f[r * 16 + c4 * 2], w4f[r * 16 + c4 * 2 + 1]);
    }
    if (t < 256) {
        int k = t;
        sPack[k] = make_float4(0.f, w1[k * 771 + 768],
                               w1[k * 771 + 769], w1[k * 771 + 770]);
        sLgb[k]  = make_float2(lng[k], lnb[k]);
        if (k < 128) sB2[k] = b2[k];
        if (k < 64)  sB3[k] = b3[k];
        if (k < 32)  { sB4[k] = b4[k]; sW5[k] = w5[k]; }
        if (k == 0)  sB5[0] = b5[0];
    }

    const int r0 = w * 16 + g, r1 = r0 + 8;

    for (int wk = blockIdx.x; wk < NWORK; wk += NBLOCKS) {
        const int i  = wk >> 2;
        const int j0 = (wk & 3) * 192;
        const int jr0 = j0 + r0, jr1 = j0 + r1;

        __syncthreads();
        if (t < 256) sPack[t].x = Ap[i * 256 + t];
        __syncthreads();

        float bxi = boxes[i * 4], byi = boxes[i * 4 + 1];
        float dy0 = byi - boxes[jr0 * 4 + 1];
        float dy1 = byi - boxes[jr1 * 4 + 1];
        float sx0 = fabsf(bxi - boxes[jr0 * 4]), sya0 = fabsf(dy0), sys0 = dy0;
        float sx1 = fabsf(bxi - boxes[jr1 * 4]), sya1 = fabsf(dy1), sys1 = dy1;

        uint32_t A1[64];
#pragma unroll
        for (int q = 0; q < 16; q++) {
            int p0 = 8 * q + tig, p1 = p0 + 4;
            float2 ai0 = unpack_bf16(attbf[i * 128 + p0]);
            float2 ai1 = unpack_bf16(attbf[i * 128 + p1]);
            float2 j00 = unpack_bf16(attbf[jr0 * 128 + p0]);
            float2 j10 = unpack_bf16(attbf[jr1 * 128 + p0]);
            float2 j01 = unpack_bf16(attbf[jr0 * 128 + p1]);
            float2 j11 = unpack_bf16(attbf[jr1 * 128 + p1]);
            A1[4 * q]     = pack_bf16(j00.x * ai0.x, j00.y * ai0.y);
            A1[4 * q + 1] = pack_bf16(j10.x * ai0.x, j10.y * ai0.y);
            A1[4 * q + 2] = pack_bf16(j01.x * ai1.x, j01.y * ai1.y);
            A1[4 * q + 3] = pack_bf16(j11.x * ai1.x, j11.y * ai1.y);
        }

        uint32_t H1[64];
        float sum0 = 0.f, sq0 = 0.f, sum1 = 0.f, sq1 = 0.f;
#pragma unroll
        for (int h = 0; h < 2; h++) {
            float acc[16][4];
#pragma unroll
            for (int ntl = 0; ntl < 16; ntl++)
#pragma unroll
                for (int q = 0; q < 4; q++) acc[ntl][q] = 0.f;

#pragma unroll
            for (int q = 0; q < 16; q++) {
                uint32_t a0 = A1[4 * q],     a1 = A1[4 * q + 1];
                uint32_t a2 = A1[4 * q + 2], a3 = A1[4 * q + 3];
#pragma unroll
                for (int ntl = 0; ntl < 16; ntl++) {
                    int n = (h * 16 + ntl) * 8 + g;
                    uint32_t b0 = W1s[n * 132 + 8 * q + tig];
                    uint32_t b1 = W1s[n * 132 + 8 * q + 4 + tig];
                    mma_bf16(acc[ntl], a0, a1, a2, a3, b0, b1);
                }
            }
#pragma unroll
            for (int ntl = 0; ntl < 16; ntl++) {
                int nt = h * 16 + ntl;
                int c0 = 8 * nt + 2 * tig;
                float4 p0 = sPack[c0], p1 = sPack[c0 + 1];
                float2 bp0 = unpack_bf16(bpbf[jr0 * 128 + 4 * nt + tig]);
                float2 bp1 = unpack_bf16(bpbf[jr1 * 128 + 4 * nt + tig]);
                float v00 = acc[ntl][0] + p0.x + sx0 * p0.y + sya0 * p0.z + sys0 * p0.w + bp0.x;
                float v01 = acc[ntl][1] + p1.x + sx0 * p1.y + sya0 * p1.z + sys0 * p1.w + bp0.y;
                float v10 = acc[ntl][2] + p0.x + sx1 * p0.y + sya1 * p0.z + sys1 * p0.w + bp1.x;
                float v11 = acc[ntl][3] + p1.x + sx1 * p1.y + sya1 * p1.z + sys1 * p1.w + bp1.y;
                v00 = fmaxf(v00, 0.f); v01 = fmaxf(v01, 0.f);
                v10 = fmaxf(v10, 0.f); v11 = fmaxf(v11, 0.f);
                sum0 += v00 + v01; sq0 += v00 * v00 + v01 * v01;
                sum1 += v10 + v11; sq1 += v10 * v10 + v11 * v11;
                int q2 = nt >> 1, off = (nt & 1) * 2;
                H1[4 * q2 + off]     = pack_bf16(v00, v01);
                H1[4 * q2 + off + 1] = pack_bf16(v10, v11);
            }
        }

#pragma unroll
        for (int o = 1; o <= 2; o <<= 1) {
            sum0 += __shfl_xor_sync(0xffffffffu, sum0, o);
            sq0  += __shfl_xor_sync(0xffffffffu, sq0,  o);
            sum1 += __shfl_xor_sync(0xffffffffu, sum1, o);
            sq1  += __shfl_xor_sync(0xffffffffu, sq1,  o);
        }
        float mu0 = sum0 * (1.f / 256.f);
        float rs0 = rsqrtf(sq0 * (1.f / 256.f) - mu0 * mu0 + 1e-5f);
        float mu1 = sum1 * (1.f / 256.f);
        float rs1 = rsqrtf(sq1 * (1.f / 256.f) - mu1 * mu1 + 1e-5f);
#pragma unroll
        for (int q = 0; q < 16; q++) {
#pragma unroll
            for (int e2 = 0; e2 < 2; e2++) {
                int col = 16 * q + 8 * e2 + 2 * tig;
                float2 gb0 = sLgb[col], gb1 = sLgb[col + 1];
#pragma unroll
                for (int e = 0; e < 2; e++) {
                    int idx = 4 * q + 2 * e2 + e;
                    float2 v = unpack_bf16(H1[idx]);
                    float m = e ? mu1 : mu0, rr = e ? rs1 : rs0;
                    H1[idx] = pack_bf16((v.x - m) * rr * gb0.x + gb0.y,
                                        (v.y - m) * rr * gb1.x + gb1.y);
                }
            }
        }

        uint32_t H2[32];
#pragma unroll
        for (int h = 0; h < 2; h++) {
            float acc[8][4];
#pragma unroll
            for (int ntl = 0; ntl < 8; ntl++)
#pragma unroll
                for (int q = 0; q < 4; q++) acc[ntl][q] = 0.f;
#pragma unroll
            for (int q = 0; q < 16; q++) {
                uint32_t a0 = H1[4 * q],     a1 = H1[4 * q + 1];
                uint32_t a2 = H1[4 * q + 2], a3 = H1[4 * q + 3];
#pragma unroll
                for (int ntl = 0; ntl < 8; ntl++) {
                    int n = (h * 8 + ntl) * 8 + g;
                    uint32_t b0 = W2s[n * 132 + 8 * q + tig];
                    uint32_t b1 = W2s[n * 132 + 8 * q + 4 + tig];
                    mma_bf16(acc[ntl], a0, a1, a2, a3, b0, b1);
                }
            }
#pragma unroll
            for (int ntl = 0; ntl < 8; ntl++) {
                int nt = h * 8 + ntl;
                int c0 = 8 * nt + 2 * tig;
                float v00 = fmaxf(acc[ntl][0] + sB2[c0], 0.f);
                float v01 = fmaxf(acc[ntl][1] + sB2[c0 + 1], 0.f);
                float v10 = fmaxf(acc[ntl][2] + sB2[c0], 0.f);
                float v11 = fmaxf(acc[ntl][3] + sB2[c0 + 1], 0.f);
                int q2 = nt >> 1, off = (nt & 1) * 2;
                H2[4 * q2 + off]     = pack_bf16(v00, v01);
                H2[4 * q2 + off + 1] = pack_bf16(v10, v11);
            }
        }

        uint32_t H3[16];
        {
            float acc[8][4];
#pragma unroll
            for (int ntl = 0; ntl < 8; ntl++)
#pragma unroll
                for (int q = 0; q < 4; q++) acc[ntl][q] = 0.f;
#pragma unroll
            for (int q = 0; q < 8; q++) {
                uint32_t a0 = H2[4 * q],     a1 = H2[4 * q + 1];
                uint32_t a2 = H2[4 * q + 2], a3 = H2[4 * q + 3];
#pragma unroll
                for (int ntl = 0; ntl < 8; ntl++) {
                    int n = ntl * 8 + g;
                    uint32_t b0 = W3s[n * 68 + 8 * q + tig];
                    uint32_t b1 = W3s[n * 68 + 8 * q + 4 + tig];
                    mma_bf16(acc[ntl], a0, a1, a2, a3, b0, b1);
                }
            }
#pragma unroll
            for (int nt = 0; nt < 8; nt++) {
                int c0 = 8 * nt + 2 * tig;
                float v00 = fmaxf(acc[nt][0] + sB3[c0], 0.f);
                float v01 = fmaxf(acc[nt][1] + sB3[c0 + 1], 0.f);
                float v10 = fmaxf(acc[nt][2] + sB3[c0], 0.f);
                float v11 = fmaxf(acc[nt][3] + sB3[c0 + 1], 0.f);
                int q2 = nt >> 1, off = (nt & 1) * 2;
                H3[4 * q2 + off]     = pack_bf16(v00, v01);
                H3[4 * q2 + off + 1] = pack_bf16(v10, v11);
            }
        }

        {
            float acc[4][4];
#pragma unroll
            for (int ntl = 0; ntl < 4; ntl++)
#pragma unroll
                for (int q = 0; q < 4; q++) acc[ntl][q] = 0.f;
#pragma unroll
            for (int q = 0; q < 4; q++) {
                uint32_t a0 = H3[4 * q],     a1 = H3[4 * q + 1];
                uint32_t a2 = H3[4 * q + 2], a3 = H3[4 * q + 3];
#pragma unroll
                for (int ntl = 0; ntl < 4; ntl++) {
                    int n = ntl * 8 + g;
                    uint32_t b0 = W4s[n * 36 + 8 * q + tig];
                    uint32_t b1 = W4s[n * 36 + 8 * q + 4 + tig];
                    mma_bf16(acc[ntl], a0, a1, a2, a3, b0, b1);
                }
            }
            float p0 = 0.f, p1 = 0.f;
#pragma unroll
            for (int nt = 0; nt < 4; nt++) {
                int c0 = 8 * nt + 2 * tig;
                p0 += fmaxf(acc[nt][0] + sB4[c0], 0.f) * sW5[c0]
                    + fmaxf(acc[nt][1] + sB4[c0 + 1], 0.f) * sW5[c0 + 1];
                p1 += fmaxf(acc[nt][2] + sB4[c0], 0.f) * sW5[c0]
                    + fmaxf(acc[nt][3] + sB4[c0 + 1], 0.f) * sW5[c0 + 1];
            }
#pragma unroll
            for (int o = 1; o <= 2; o <<= 1) {
                p0 += __shfl_xor_sync(0xffffffffu, p0, o);
                p1 += __shfl_xor_sync(0xffffffffu, p1, o);
            }
            if (tig == 0) {
                float bb = sB5[0];
                out[i * 768 + jr0] = (jr0 == i) ? -1000000000.0f : p0 + bb;
                out[i * 768 + jr1] = (jr1 == i) ? -1000000000.0f : p1 + bb;
            }
        }
    }
}

// ---------------- host launch ------------------------------------------------
extern "C" void kernel_launch(void* const* d_in, const int* in_sizes, int n_in,
                              void* d_out, int out_size)
{
    (void)in_sizes; (void)n_in; (void)out_size;
    const float* features = (const float*)d_in[0];
    const float* boxes    = (const float*)d_in[1];
    const float* in_w     = (const float*)d_in[2];
    const float* in_b     = (const float*)d_in[3];
    const float* out_w    = (const float*)d_in[4];
    const float* out_b    = (const float*)d_in[5];
    const float* w1       = (const float*)d_in[6];
    const float* b1       = (const float*)d_in[7];
    const float* lng      = (const float*)d_in[8];
    const float* lnb      = (const float*)d_in[9];
    const float* w2       = (const float*)d_in[10];
    const float* b2       = (const float*)d_in[11];
    const float* w3       = (const float*)d_in[12];
    const float* b3       = (const float*)d_in[13];
    const float* w4       = (const float*)d_in[14];
    const float* b4       = (const float*)d_in[15];
    const float* w5       = (const float*)d_in[16];
    const float* b5       = (const float*)d_in[17];
    float* out = (float*)d_out;

    void *attbf, *bpbf, *w1ab, *w1c;
    float* Apb;
    cudaGetSymbolAddress(&attbf, g_att_bf);
    cudaGetSymbolAddress(&bpbf,  g_Bp_bf);
    cudaGetSymbolAddress(&w1ab,  g_w1ab_bf);
    cudaGetSymbolAddress(&w1c,   g_w1c_bf);
    cudaGetSymbolAddress((void**)&Apb, g_Ap);

    cudaFuncSetAttribute(gemm_qkv,
                         cudaFuncAttributeMaxDynamicSharedMemorySize, GEMM_SMEM_BYTES);
    cudaFuncSetAttribute(gemm_att,
                         cudaFuncAttributeMaxDynamicSharedMemorySize, ATT_SMEM_BYTES);
    cudaFuncSetAttribute(gemm_apbp,
                         cudaFuncAttributeMaxDynamicSharedMemorySize, GEMM_SMEM_BYTES);
    cudaFuncSetAttribute(fused_pairs_reg,
                         cudaFuncAttributeMaxDynamicSharedMemorySize, SMEM_BYTES);

    // 1. qkv = feat @ in_w^T + in_b  (+vT scatter, +coalesced w1 cvt tail)
    gemm_qkv<<<dim3(6, 6), 256, GEMM_SMEM_BYTES>>>(
        (const float4*)features, (const float4*)in_w, in_b, w1);

    // 2. split-KV flash attention (3 splits)
    attn_flash<<<dim3(6, 8, 3), 256>>>();

    // 3. att = combine(osplit) @ out_w^T + out_b
    gemm_att<<<dim3(2, 6), 256, ATT_SMEM_BYTES>>>(
        (const float4*)out_w, out_b);

    // 4. [Ap | Bp] = att @ w1ab_bf^T + [b1|0]
    gemm_apbp<<<dim3(4, 6), 256, GEMM_SMEM_BYTES>>>(
        (const uint4*)attbf, (const uint4*)w1ab, b1);

    // 5. persistent fused all-pairs MLP (W1 from bf16; w2/w3/w4 inline cvt)
    fused_pairs_reg<<<NBLOCKS, 384, SMEM_BYTES>>>(
        boxes, w1, Apb,
        (const uint32_t*)attbf, (const uint32_t*)bpbf,
        (const uint4*)w1c,
        (const float4*)w2, (const float4*)w3, (const float4*)w4,
        lng, lnb, b2, b3, b4, w5, b5, out);
}